// round 6
// baseline (speedup 1.0000x reference)
#include <cuda_runtime.h>
#include <math.h>

#define BATCH    32768
#define EMBED    128
#define MAX_PATH 20
#define VEC4     (EMBED / 4)          // 32 float4 per row

#define THREADS  256
#define WARPS_PER_BLOCK (THREADS / 32)
#define NBLOCKS  (BATCH / WARPS_PER_BLOCK)   // 4096

// Fixed-point accumulator: integer adds are associative -> deterministic.
#define FXP_SCALE 17179869184.0f          // 2^34
#define FXP_INV   (1.0 / 17179869184.0)   // 2^-34

__device__ unsigned long long g_acc   = 0ull;
__device__ unsigned int       g_count = 0u;

// v4 table gather with L2 cache-hint policy (tables: evict_last)
__device__ __forceinline__ float4 ldg_pol4(const float4* __restrict__ p,
                                           unsigned long long pol)
{
    float4 r;
    asm("ld.global.nc.L2::cache_hint.v4.f32 {%0,%1,%2,%3}, [%4], %5;"
        : "=f"(r.x), "=f"(r.y), "=f"(r.z), "=f"(r.w)
        : "l"(p), "l"(pol));
    return r;
}

// scalar streaming loads with evict_first policy
__device__ __forceinline__ int ldg_pol_i(const int* __restrict__ p,
                                         unsigned long long pol)
{
    int r;
    asm("ld.global.nc.L2::cache_hint.b32 %0, [%1], %2;"
        : "=r"(r) : "l"(p), "l"(pol));
    return r;
}
__device__ __forceinline__ float ldg_pol_f(const float* __restrict__ p,
                                           unsigned long long pol)
{
    float r;
    asm("ld.global.nc.L2::cache_hint.f32 %0, [%1], %2;"
        : "=f"(r) : "l"(p), "l"(pol));
    return r;
}

__global__ __launch_bounds__(THREADS)
void hs_loss_kernel(const int* __restrict__ center,
                    const int* __restrict__ target,
                    const float4* __restrict__ in_emb,     // (V, 32) float4
                    const float4* __restrict__ inner_vec,  // (N_INNER, 32) float4
                    const int* __restrict__ paths,         // (V, 20)
                    const float* __restrict__ codes,       // (V, 20)
                    float* __restrict__ out)
{
    const int lane = threadIdx.x & 31;
    const int wid  = threadIdx.x >> 5;
    const int b    = blockIdx.x * WARPS_PER_BLOCK + wid;   // one warp = one batch element

    unsigned long long pol_keep, pol_stream;
    asm("createpolicy.fractional.L2::evict_last.b64 %0, 1.0;"  : "=l"(pol_keep));
    asm("createpolicy.fractional.L2::evict_first.b64 %0, 1.0;" : "=l"(pol_stream));

    const int c = ldg_pol_i(&center[b], pol_stream);
    const int t = ldg_pol_i(&target[b], pol_stream);

    // center embedding: 4 dims per lane, coalesced 512B per warp
    const float4 h = ldg_pol4(&in_emb[(unsigned)c * VEC4 + lane], pol_keep);

    // lane l (<20) owns path position l. masks == |codes| by construction.
    int   p  = 0;
    float cd = 0.0f;
    if (lane < MAX_PATH) {
        const int off = t * MAX_PATH + lane;
        p  = ldg_pol_i(&paths[off], pol_stream);
        cd = ldg_pol_f(&codes[off], pol_stream);
    }

    // All 20 gathers issued before the reduces: two partial arrays so the
    // second phase's loads are independent of the first phase's fold.
    float va[16], vb[16];
    #pragma unroll
    for (int k = 10; k < 16; ++k) { va[k] = 0.0f; vb[k] = 0.0f; }

    #pragma unroll
    for (int j = 0; j < 10; ++j) {
        const int pl = __shfl_sync(0xffffffffu, p, j);
        const float4 iv = ldg_pol4(&inner_vec[(unsigned)pl * VEC4 + lane], pol_keep);
        float s = iv.x * h.x;
        s = fmaf(iv.y, h.y, s);
        s = fmaf(iv.z, h.z, s);
        s = fmaf(iv.w, h.w, s);
        va[j] = s;
    }
    #pragma unroll
    for (int j = 0; j < 10; ++j) {
        const int pl = __shfl_sync(0xffffffffu, p, 10 + j);
        const float4 iv = ldg_pol4(&inner_vec[(unsigned)pl * VEC4 + lane], pol_keep);
        float s = iv.x * h.x;
        s = fmaf(iv.y, h.y, s);
        s = fmaf(iv.z, h.z, s);
        s = fmaf(iv.w, h.w, s);
        vb[j] = s;
    }

    // transpose-reduce each phase: lane (i&15) ends with dot of its position
    float res0, res1;
    #pragma unroll
    for (int bi = 0; bi < 2; ++bi) {
        float* v = bi ? vb : va;
        #pragma unroll
        for (int k = 0; k < 10; ++k)
            v[k] += __shfl_xor_sync(0xffffffffu, v[k], 16);
        #pragma unroll
        for (int half = 8; half >= 1; half >>= 1) {
            const bool hi = (lane & half) != 0;
            #pragma unroll
            for (int k = 0; k < half; ++k) {
                const float send = hi ? v[k] : v[k + half];
                const float recv = __shfl_xor_sync(0xffffffffu, send, half);
                v[k] = (hi ? v[k + half] : v[k]) + recv;
            }
        }
        if (bi == 0) res0 = v[0]; else res1 = v[0];
    }

    // lanes 0..9 own positions 0..9 (res0); lanes 16..25 own 10..19 (res1)
    const int  sub   = lane & 15;
    const int  grp   = lane >> 4;
    const bool valid = (sub < 10);
    const int  pos   = grp * 10 + sub;               // < 26, safe shfl index
    const float cdl  = __shfl_sync(0xffffffffu, cd, pos);
    const float dot  = grp ? res1 : res0;

    float loss = 0.0f;
    if (valid) {
        const float x  = cdl * dot;
        const float lp = fminf(x, 0.0f) - __logf(1.0f + __expf(-fabsf(x)));
        loss = -lp * (cdl * cdl);                    // cdl = 0 on padding
    }

    // warp total (5 shuffles)
    #pragma unroll
    for (int o = 16; o > 0; o >>= 1)
        loss += __shfl_xor_sync(0xffffffffu, loss, o);

    // block reduce: one value per warp
    __shared__ float sbuf[WARPS_PER_BLOCK];
    if (lane == 0) sbuf[wid] = loss;
    __syncthreads();

    if (threadIdx.x == 0) {
        float s = 0.0f;
        #pragma unroll
        for (int i = 0; i < WARPS_PER_BLOCK; ++i) s += sbuf[i];

        // deterministic fixed-point global accumulation
        const long long q = llrintf(s * FXP_SCALE);
        atomicAdd(&g_acc, (unsigned long long)q);
        __threadfence();

        const unsigned int ticket = atomicAdd(&g_count, 1u);
        if (ticket == NBLOCKS - 1) {
            const long long total = (long long)g_acc;
            out[0] = (float)((double)total * FXP_INV / (double)BATCH);
            g_acc   = 0ull;
            g_count = 0u;
        }
    }
}

extern "C" void kernel_launch(void* const* d_in, const int* in_sizes, int n_in,
                              void* d_out, int out_size)
{
    const int*    center    = (const int*)   d_in[0];
    const int*    target    = (const int*)   d_in[1];
    const float4* in_emb    = (const float4*)d_in[2];
    const float4* inner_vec = (const float4*)d_in[3];
    const int*    paths     = (const int*)   d_in[4];
    const float*  codes     = (const float*) d_in[5];
    // d_in[6] (masks) intentionally unused: masks == |codes|
    float*        out       = (float*)       d_out;

    hs_loss_kernel<<<NBLOCKS, THREADS>>>(center, target, in_emb, inner_vec,
                                         paths, codes, out);
}

// round 7
// speedup vs baseline: 1.0667x; 1.0667x over previous
#include <cuda_runtime.h>
#include <math.h>

#define BATCH    32768
#define EMBED    128
#define MAX_PATH 20
#define VEC4     (EMBED / 4)          // 32 float4 per row

#define THREADS  128
#define WARPS_PER_BLOCK (THREADS / 32)          // 4
#define NBLOCKS  (BATCH / WARPS_PER_BLOCK)      // 8192

// Fixed-point accumulator: integer adds are associative -> deterministic.
#define FXP_SCALE 17179869184.0f          // 2^34
#define FXP_INV   (1.0 / 17179869184.0)   // 2^-34

__device__ unsigned long long g_acc   = 0ull;
__device__ unsigned int       g_count = 0u;

// Volatile v4 gather: ordered among themselves, cannot be sunk/re-issued.
__device__ __forceinline__ float4 ldg_v4(const float4* __restrict__ p)
{
    float4 r;
    asm volatile("ld.global.nc.v4.f32 {%0,%1,%2,%3}, [%4];"
                 : "=f"(r.x), "=f"(r.y), "=f"(r.z), "=f"(r.w)
                 : "l"(p));
    return r;
}

__device__ __forceinline__ float dot4(const float4 a, const float4 b)
{
    float s = a.x * b.x;
    s = fmaf(a.y, b.y, s);
    s = fmaf(a.z, b.z, s);
    s = fmaf(a.w, b.w, s);
    return s;
}

__global__ __launch_bounds__(THREADS)
void hs_loss_kernel(const int* __restrict__ center,
                    const int* __restrict__ target,
                    const float4* __restrict__ in_emb,     // (V, 32) float4
                    const float4* __restrict__ inner_vec,  // (N_INNER, 32) float4
                    const int* __restrict__ paths,         // (V, 20)
                    const float* __restrict__ codes,       // (V, 20)
                    float* __restrict__ out)
{
    const int lane = threadIdx.x & 31;
    const int wid  = threadIdx.x >> 5;
    const int b    = blockIdx.x * WARPS_PER_BLOCK + wid;   // one warp = one batch element

    const int c = center[b];
    const int t = target[b];

    // center embedding: 4 dims per lane, coalesced 512B per warp
    const float4 h = ldg_v4(&in_emb[(unsigned)c * VEC4 + lane]);

    // lane l (<20) owns path position l. masks == |codes| by construction.
    int   p  = 0;
    float cd = 0.0f;
    if (lane < MAX_PATH) {
        const int off = t * MAX_PATH + lane;
        p  = paths[off];
        cd = codes[off];
    }

    // Issue ALL 20 gathers (volatile -> ordered, cannot be serialized away).
    float4 A[10], B[10];
    #pragma unroll
    for (int j = 0; j < 10; ++j) {
        const int pl = __shfl_sync(0xffffffffu, p, j);
        A[j] = ldg_v4(&inner_vec[(unsigned)pl * VEC4 + lane]);
    }
    #pragma unroll
    for (int j = 0; j < 10; ++j) {
        const int pl = __shfl_sync(0xffffffffu, p, 10 + j);
        B[j] = ldg_v4(&inner_vec[(unsigned)pl * VEC4 + lane]);
    }

    // Consume in REVERSE: first FMA needs the LAST load, forcing all 20
    // float4 destinations live simultaneously -> ptxas must batch the issues.
    float va[16], vb[16];
    #pragma unroll
    for (int k = 10; k < 16; ++k) { va[k] = 0.0f; vb[k] = 0.0f; }
    #pragma unroll
    for (int j = 9; j >= 0; --j) vb[j] = dot4(B[j], h);
    #pragma unroll
    for (int j = 9; j >= 0; --j) va[j] = dot4(A[j], h);

    // transpose-reduce each phase: lane (i&15) ends with dot of its position
    float res0, res1;
    #pragma unroll
    for (int bi = 0; bi < 2; ++bi) {
        float* v = bi ? vb : va;
        #pragma unroll
        for (int k = 0; k < 10; ++k)
            v[k] += __shfl_xor_sync(0xffffffffu, v[k], 16);
        #pragma unroll
        for (int half = 8; half >= 1; half >>= 1) {
            const bool hi = (lane & half) != 0;
            #pragma unroll
            for (int k = 0; k < half; ++k) {
                const float send = hi ? v[k] : v[k + half];
                const float recv = __shfl_xor_sync(0xffffffffu, send, half);
                v[k] = (hi ? v[k + half] : v[k]) + recv;
            }
        }
        if (bi == 0) res0 = v[0]; else res1 = v[0];
    }

    // lanes 0..9 own positions 0..9 (res0); lanes 16..25 own 10..19 (res1)
    const int  sub   = lane & 15;
    const int  grp   = lane >> 4;
    const bool valid = (sub < 10);
    const int  pos   = grp * 10 + sub;               // < 26, safe shfl index
    const float cdl  = __shfl_sync(0xffffffffu, cd, pos);
    const float dot  = grp ? res1 : res0;

    float loss = 0.0f;
    if (valid) {
        const float x  = cdl * dot;
        const float lp = fminf(x, 0.0f) - __logf(1.0f + __expf(-fabsf(x)));
        loss = -lp * (cdl * cdl);                    // cdl = 0 on padding
    }

    // warp total (5 shuffles)
    #pragma unroll
    for (int o = 16; o > 0; o >>= 1)
        loss += __shfl_xor_sync(0xffffffffu, loss, o);

    // block reduce: one value per warp
    __shared__ float sbuf[WARPS_PER_BLOCK];
    if (lane == 0) sbuf[wid] = loss;
    __syncthreads();

    if (threadIdx.x == 0) {
        float s = 0.0f;
        #pragma unroll
        for (int i = 0; i < WARPS_PER_BLOCK; ++i) s += sbuf[i];

        // deterministic fixed-point global accumulation
        const long long q = llrintf(s * FXP_SCALE);
        atomicAdd(&g_acc, (unsigned long long)q);
        __threadfence();

        const unsigned int ticket = atomicAdd(&g_count, 1u);
        if (ticket == NBLOCKS - 1) {
            const long long total = (long long)g_acc;
            out[0] = (float)((double)total * FXP_INV / (double)BATCH);
            g_acc   = 0ull;
            g_count = 0u;
        }
    }
}

extern "C" void kernel_launch(void* const* d_in, const int* in_sizes, int n_in,
                              void* d_out, int out_size)
{
    const int*    center    = (const int*)   d_in[0];
    const int*    target    = (const int*)   d_in[1];
    const float4* in_emb    = (const float4*)d_in[2];
    const float4* inner_vec = (const float4*)d_in[3];
    const int*    paths     = (const int*)   d_in[4];
    const float*  codes     = (const float*) d_in[5];
    // d_in[6] (masks) intentionally unused: masks == |codes|
    float*        out       = (float*)       d_out;

    hs_loss_kernel<<<NBLOCKS, THREADS>>>(center, target, in_emb, inner_vec,
                                         paths, codes, out);
}